// round 3
// baseline (speedup 1.0000x reference)
#include <cuda_runtime.h>
#include <math.h>

#define D_DIM 1024
#define F_DIM 4096
#define E_DIM 8
#define NTOK  16384               // B*S
#define NCH   256                 // chunks over F for kernel A
#define ROWS_PER_CH (F_DIM/NCH)   // 16
#define NG    16                  // stage-1 groups
#define CH_PER_G (NCH/NG)         // 16

// ---------------- device scratch ----------------
__device__ __align__(16) float g_part [NCH][5][D_DIM];
__device__ __align__(16) float g_part2[NG ][5][D_DIM];
__device__ __align__(16) float g_stats[5][D_DIM];   // mb, md, cbb, cbd, cdd
__device__ float g_bias_mean;

__device__ __forceinline__ void acc4(float4& s, float4 v)           { s.x += v.x; s.y += v.y; s.z += v.z; s.w += v.w; }
__device__ __forceinline__ void fma4(float4& s, float4 a, float4 b) { s.x = fmaf(a.x,b.x,s.x); s.y = fmaf(a.y,b.y,s.y); s.z = fmaf(a.z,b.z,s.z); s.w = fmaf(a.w,b.w,s.w); }

// ---------------- kernel A: column stats of W_base / W_delta -------------
// grid NCH, block 256 (thread = one float4 column). Deep MLP via unroll.
__global__ void __launch_bounds__(256) k_reduceW(const float* __restrict__ Wb,
                                                 const float* __restrict__ Wd) {
    const int q = threadIdx.x;    // float4 column 0..255
    const float4* pb = reinterpret_cast<const float4*>(Wb) + (size_t)blockIdx.x * ROWS_PER_CH * 256 + q;
    const float4* pd = reinterpret_cast<const float4*>(Wd) + (size_t)blockIdx.x * ROWS_PER_CH * 256 + q;
    float4 sb = {0,0,0,0}, sd = {0,0,0,0}, sbb = {0,0,0,0}, sbd = {0,0,0,0}, sdd = {0,0,0,0};
#pragma unroll 8
    for (int i = 0; i < ROWS_PER_CH; i++) {
        float4 b = pb[(size_t)i * 256];
        float4 w = pd[(size_t)i * 256];
        acc4(sb, b); acc4(sd, w);
        fma4(sbb, b, b); fma4(sbd, b, w); fma4(sdd, w, w);
    }
    const int c = blockIdx.x;
    *reinterpret_cast<float4*>(&g_part[c][0][q*4]) = sb;
    *reinterpret_cast<float4*>(&g_part[c][1][q*4]) = sd;
    *reinterpret_cast<float4*>(&g_part[c][2][q*4]) = sbb;
    *reinterpret_cast<float4*>(&g_part[c][3][q*4]) = sbd;
    *reinterpret_cast<float4*>(&g_part[c][4][q*4]) = sdd;
}

// ---------------- kernel B1: stage-1 chunk reduce --------------------------
// grid (8 colblocks, NG groups), block 32. One f4-column per thread.
__global__ void k_reduce1(void) {
    const int q = blockIdx.x * 32 + threadIdx.x;   // f4 column 0..255
    const int g = blockIdx.y;
    float4 s[5];
#pragma unroll
    for (int k = 0; k < 5; k++) s[k] = make_float4(0,0,0,0);
#pragma unroll
    for (int c = g * CH_PER_G; c < (g + 1) * CH_PER_G; c++) {
#pragma unroll
        for (int k = 0; k < 5; k++)
            acc4(s[k], *reinterpret_cast<const float4*>(&g_part[c][k][q*4]));
    }
#pragma unroll
    for (int k = 0; k < 5; k++)
        *reinterpret_cast<float4*>(&g_part2[g][k][q*4]) = s[k];
}

// ---------------- kernel B2: finalize centered stats + bias mean -----------
// grid 8, block 32. One f4-column per thread. Block 0 also reduces bias.
__global__ void k_finalize(const float* __restrict__ bias) {
    const int q = blockIdx.x * 32 + threadIdx.x;
    float4 s[5];
#pragma unroll
    for (int k = 0; k < 5; k++) s[k] = make_float4(0,0,0,0);
#pragma unroll
    for (int g = 0; g < NG; g++) {
#pragma unroll
        for (int k = 0; k < 5; k++)
            acc4(s[k], *reinterpret_cast<const float4*>(&g_part2[g][k][q*4]));
    }
    const float inv = 1.0f / (float)F_DIM;
    float4 mb, md, cbb, cbd, cdd;
    mb.x = s[0].x*inv; mb.y = s[0].y*inv; mb.z = s[0].z*inv; mb.w = s[0].w*inv;
    md.x = s[1].x*inv; md.y = s[1].y*inv; md.z = s[1].z*inv; md.w = s[1].w*inv;
    cbb.x = s[2].x*inv - mb.x*mb.x; cbb.y = s[2].y*inv - mb.y*mb.y;
    cbb.z = s[2].z*inv - mb.z*mb.z; cbb.w = s[2].w*inv - mb.w*mb.w;
    cbd.x = s[3].x*inv - mb.x*md.x; cbd.y = s[3].y*inv - mb.y*md.y;
    cbd.z = s[3].z*inv - mb.z*md.z; cbd.w = s[3].w*inv - mb.w*md.w;
    cdd.x = s[4].x*inv - md.x*md.x; cdd.y = s[4].y*inv - md.y*md.y;
    cdd.z = s[4].z*inv - md.z*md.z; cdd.w = s[4].w*inv - md.w*md.w;
    *reinterpret_cast<float4*>(&g_stats[0][q*4]) = mb;
    *reinterpret_cast<float4*>(&g_stats[1][q*4]) = md;
    *reinterpret_cast<float4*>(&g_stats[2][q*4]) = cbb;
    *reinterpret_cast<float4*>(&g_stats[3][q*4]) = cbd;
    *reinterpret_cast<float4*>(&g_stats[4][q*4]) = cdd;

    if (blockIdx.x == 0) {
        // one warp reduces bias[4096] via float4 + shuffles
        const float4* b4 = reinterpret_cast<const float4*>(bias);
        float s0 = 0.f;
#pragma unroll 8
        for (int i = threadIdx.x; i < F_DIM / 4; i += 32) {
            float4 v = b4[i];
            s0 += (v.x + v.y) + (v.z + v.w);
        }
#pragma unroll
        for (int o = 16; o > 0; o >>= 1) s0 += __shfl_xor_sync(0xffffffffu, s0, o);
        if (threadIdx.x == 0) g_bias_mean = s0 * inv;
    }
}

// ---------------- kernel C: fused router (5-dot, smem stats) ---------------
// 256-thread blocks, warp handles 4 tokens, scalar f32 accumulators.
__global__ void __launch_bounds__(256) k_router(const float* __restrict__ x,
                                                const float* __restrict__ alpha,
                                                const float* __restrict__ beta,
                                                float* __restrict__ out) {
    __shared__ __align__(16) float sh[5][D_DIM];     // 20 KB
    __shared__ float sred[8][4][5];

    // cooperative stats load (each thread: 5 float4)
    {
        const int q = threadIdx.x;                   // 0..255 f4 column
#pragma unroll
        for (int k = 0; k < 5; k++) {
            float4 v = *reinterpret_cast<const float4*>(&g_stats[k][q*4]);
            *reinterpret_cast<float4*>(&sh[k][q*4]) = v;
        }
    }
    __syncthreads();

    const int lane = threadIdx.x & 31;
    const int wid  = threadIdx.x >> 5;
    const int tok0 = (blockIdx.x * 8 + wid) * 4;
    const float* xp = x + (size_t)tok0 * D_DIM;

    float a0[4], a1[4], a2[4], a3[4], a4[4];
#pragma unroll
    for (int t = 0; t < 4; t++) { a0[t]=0.f; a1[t]=0.f; a2[t]=0.f; a3[t]=0.f; a4[t]=0.f; }

#pragma unroll 2
    for (int c = 0; c < 8; c++) {
        const int off = c * 128 + lane * 4;
        // batch the 4 global loads first for MLP
        float4 xv0 = *reinterpret_cast<const float4*>(xp + 0 * D_DIM + off);
        float4 xv1 = *reinterpret_cast<const float4*>(xp + 1 * D_DIM + off);
        float4 xv2 = *reinterpret_cast<const float4*>(xp + 2 * D_DIM + off);
        float4 xv3 = *reinterpret_cast<const float4*>(xp + 3 * D_DIM + off);
        float4 s0 = *reinterpret_cast<const float4*>(&sh[0][off]);
        float4 s1 = *reinterpret_cast<const float4*>(&sh[1][off]);
        float4 s2 = *reinterpret_cast<const float4*>(&sh[2][off]);
        float4 s3 = *reinterpret_cast<const float4*>(&sh[3][off]);
        float4 s4 = *reinterpret_cast<const float4*>(&sh[4][off]);
        float4 xv[4] = {xv0, xv1, xv2, xv3};
#pragma unroll
        for (int t = 0; t < 4; t++) {
            float4 v = xv[t];
            float4 q;
            q.x = v.x * v.x; q.y = v.y * v.y; q.z = v.z * v.z; q.w = v.w * v.w;
            a0[t] = fmaf(v.x, s0.x, fmaf(v.y, s0.y, fmaf(v.z, s0.z, fmaf(v.w, s0.w, a0[t]))));
            a1[t] = fmaf(v.x, s1.x, fmaf(v.y, s1.y, fmaf(v.z, s1.z, fmaf(v.w, s1.w, a1[t]))));
            a2[t] = fmaf(q.x, s2.x, fmaf(q.y, s2.y, fmaf(q.z, s2.z, fmaf(q.w, s2.w, a2[t]))));
            a3[t] = fmaf(q.x, s3.x, fmaf(q.y, s3.y, fmaf(q.z, s3.z, fmaf(q.w, s3.w, a3[t]))));
            a4[t] = fmaf(q.x, s4.x, fmaf(q.y, s4.y, fmaf(q.z, s4.z, fmaf(q.w, s4.w, a4[t]))));
        }
    }

    // warp reductions: 20 scalars per warp, unique landing lane per (t,s)
#pragma unroll
    for (int t = 0; t < 4; t++) {
        float v0 = a0[t], v1 = a1[t], v2 = a2[t], v3 = a3[t], v4 = a4[t];
#pragma unroll
        for (int o = 16; o > 0; o >>= 1) {
            v0 += __shfl_xor_sync(0xffffffffu, v0, o);
            v1 += __shfl_xor_sync(0xffffffffu, v1, o);
            v2 += __shfl_xor_sync(0xffffffffu, v2, o);
            v3 += __shfl_xor_sync(0xffffffffu, v3, o);
            v4 += __shfl_xor_sync(0xffffffffu, v4, o);
        }
        if (lane == t * 5 + 0) sred[wid][t][0] = v0;
        if (lane == t * 5 + 1) sred[wid][t][1] = v1;
        if (lane == t * 5 + 2) sred[wid][t][2] = v2;
        if (lane == t * 5 + 3) sred[wid][t][3] = v3;
        if (lane == t * 5 + 4) sred[wid][t][4] = v4;
    }
    __syncthreads();

    // epilogue: one thread per token (32 tokens/block)
    if (threadIdx.x < 32) {
        const int w = threadIdx.x >> 2;
        const int t = threadIdx.x & 3;
        const int tok = blockIdx.x * 32 + threadIdx.x;
        const float bm = g_bias_mean;

        const float d_mb = sred[w][t][0];
        const float d_md = sred[w][t][1];
        const float d_bb = sred[w][t][2];
        const float d_bd = sred[w][t][3];
        const float d_dd = sred[w][t][4];

        float l[E_DIM];
#pragma unroll
        for (int e = 0; e < E_DIM; e++) {
            float a = __ldg(&alpha[e]);
            float b = __ldg(&beta[e]);
            float mu = fmaf(a, d_mb, fmaf(b, d_md, bm));
            float va = fmaf(a * a, d_bb, fmaf(2.0f * a * b, d_bd, b * b * d_dd));
            float z  = mu * rsqrtf(va + 1e-8f) * 0.70710678118654752f;
            l[e] = erff(z);
        }

        // top-2 (strict >, ties keep lower index — matches lax.top_k)
        int i1 = -1, i2 = -1;
        float v1 = -2.0f, v2 = -2.0f;
#pragma unroll
        for (int e = 0; e < E_DIM; e++) {
            float val = l[e];
            if (val > v1)      { v2 = v1; i2 = i1; v1 = val; i1 = e; }
            else if (val > v2) { v2 = val; i2 = e; }
        }
        float w2 = 1.0f / (1.0f + expf(v1 - v2));
        float w1 = 1.0f - w2;

        float wv[E_DIM];
#pragma unroll
        for (int e = 0; e < E_DIM; e++)
            wv[e] = (e == i1) ? w1 : ((e == i2) ? w2 : 0.0f);

        float4* ow = reinterpret_cast<float4*>(out + (size_t)tok * E_DIM);
        ow[0] = make_float4(wv[0], wv[1], wv[2], wv[3]);
        ow[1] = make_float4(wv[4], wv[5], wv[6], wv[7]);
        float4* ol = reinterpret_cast<float4*>(out + (size_t)NTOK * E_DIM + (size_t)tok * E_DIM);
        ol[0] = make_float4(l[0], l[1], l[2], l[3]);
        ol[1] = make_float4(l[4], l[5], l[6], l[7]);
    }
}

// ---------------- launch ---------------------------------------------------
extern "C" void kernel_launch(void* const* d_in, const int* in_sizes, int n_in,
                              void* d_out, int out_size) {
    const float* x     = (const float*)d_in[0];
    const float* Wb    = (const float*)d_in[1];
    const float* Wd    = (const float*)d_in[2];
    const float* bias  = (const float*)d_in[3];
    const float* alpha = (const float*)d_in[4];
    const float* beta  = (const float*)d_in[5];
    float* out = (float*)d_out;

    k_reduceW<<<NCH, 256>>>(Wb, Wd);
    k_reduce1<<<dim3(8, NG), 32>>>();
    k_finalize<<<8, 32>>>(bias);
    k_router<<<NTOK / 32, 256>>>(x, alpha, beta, out);
}